// round 2
// baseline (speedup 1.0000x reference)
#include <cuda_runtime.h>
#include <cstdint>

// Problem constants
#define BB   128      // batch
#define IN_  1024
#define OUT_ 1024
#define NS   16       // i-dimension splits
#define LI   (IN_/NS) // 64 i-values per split
#define NB   16       // batches per block (doubled: halves sig/mu L2 traffic)
#define NBG  (BB/NB)  // 8 b-groups
#define O4   (OUT_/4) // 256 float4 lanes over OUT

// Scratch (allocation-free rule: __device__ globals)
__device__ float g_sigma[IN_ * OUT_];            // softplus(ro), 4 MB
__device__ float g_partial[NS * BB * OUT_];      // per-split partial sums, 8 MB

// ---------------------------------------------------------------------------
// Kernel 0: sigma = log1p(exp(ro)). 4 independent float4 per thread for MLP.
// ---------------------------------------------------------------------------
__global__ __launch_bounds__(256)
void sigma_kernel(const float* __restrict__ ro) {
    const int base = (blockIdx.x * blockDim.x + threadIdx.x) * 4;  // 4 float4s
    const float4* r4 = reinterpret_cast<const float4*>(ro);
    float4* s4 = reinterpret_cast<float4*>(g_sigma);
    float4 r[4];
#pragma unroll
    for (int k = 0; k < 4; k++) r[k] = r4[base + k];
#pragma unroll
    for (int k = 0; k < 4; k++) {
        float4 s;
        s.x = log1pf(__expf(r[k].x));
        s.y = log1pf(__expf(r[k].y));
        s.z = log1pf(__expf(r[k].z));
        s.w = log1pf(__expf(r[k].w));
        s4[base + k] = s;
    }
}

// ---------------------------------------------------------------------------
// Kernel 1: main streaming kernel.
// Block (s, bg): i in [s*LI, (s+1)*LI), batches b in [bg*NB, bg*NB+NB),
// full OUT tile (256 threads x float4). sig/mu loaded once per i, reused
// across NB=16 batches (16x L2 traffic reduction on sig/mu). eps streamed
// once from DRAM, 16 LDG.128 per iter in two staged batches of 8.
// ---------------------------------------------------------------------------
__global__ __launch_bounds__(256)
void main_kernel(const float* __restrict__ x,
                 const float* __restrict__ mu,
                 const float* __restrict__ eps) {
    __shared__ float xs[NB][LI];   // 4 KB

    const int s  = blockIdx.x;     // 0..NS-1
    const int bg = blockIdx.y;     // 0..NBG-1
    const int t  = threadIdx.x;    // 0..255 -> o = 4t..4t+3
    const int i0 = s * LI;
    const int b0 = bg * NB;

    // Cooperative load of the x tile: x[b0..b0+NB, i0..i0+LI)
    for (int k = t; k < NB * LI; k += 256) {
        int bb = k / LI;
        int ii = k % LI;
        xs[bb][ii] = x[(size_t)(b0 + bb) * IN_ + i0 + ii];
    }
    __syncthreads();

    float4 acc[NB];
#pragma unroll
    for (int bb = 0; bb < NB; bb++) acc[bb] = make_float4(0.f, 0.f, 0.f, 0.f);

    const float4* sig4 = reinterpret_cast<const float4*>(g_sigma) + (size_t)i0 * O4 + t;
    const float4* mu4  = reinterpret_cast<const float4*>(mu)      + (size_t)i0 * O4 + t;
    const float4* ep4  = reinterpret_cast<const float4*>(eps)
                         + ((size_t)b0 * IN_ + i0) * O4 + t;

#pragma unroll 1
    for (int ii = 0; ii < LI; ii++) {
        const float4 sg = sig4[(size_t)ii * O4];
        const float4 mw = mu4[(size_t)ii * O4];

        // Two staged batches of 8 independent DRAM loads to cap live regs
        // while keeping MLP high (second batch issues before first is consumed).
        float4 ev0[8], ev1[8];
#pragma unroll
        for (int bb = 0; bb < 8; bb++)
            ev0[bb] = ep4[((size_t)bb * IN_ + ii) * O4];
#pragma unroll
        for (int bb = 0; bb < 8; bb++)
            ev1[bb] = ep4[((size_t)(bb + 8) * IN_ + ii) * O4];

#pragma unroll
        for (int bb = 0; bb < 8; bb++) {
            const float xr = xs[bb][ii];
            const float4 e = ev0[bb];
            acc[bb].x = fmaf(xr, fmaf(e.x, sg.x, mw.x), acc[bb].x);
            acc[bb].y = fmaf(xr, fmaf(e.y, sg.y, mw.y), acc[bb].y);
            acc[bb].z = fmaf(xr, fmaf(e.z, sg.z, mw.z), acc[bb].z);
            acc[bb].w = fmaf(xr, fmaf(e.w, sg.w, mw.w), acc[bb].w);
        }
#pragma unroll
        for (int bb = 0; bb < 8; bb++) {
            const float xr = xs[bb + 8][ii];
            const float4 e = ev1[bb];
            acc[bb + 8].x = fmaf(xr, fmaf(e.x, sg.x, mw.x), acc[bb + 8].x);
            acc[bb + 8].y = fmaf(xr, fmaf(e.y, sg.y, mw.y), acc[bb + 8].y);
            acc[bb + 8].z = fmaf(xr, fmaf(e.z, sg.z, mw.z), acc[bb + 8].z);
            acc[bb + 8].w = fmaf(xr, fmaf(e.w, sg.w, mw.w), acc[bb + 8].w);
        }
    }

    // Deterministic partials: P[s][b][o]
    float4* P = reinterpret_cast<float4*>(g_partial) + (size_t)s * BB * O4 + t;
#pragma unroll
    for (int bb = 0; bb < NB; bb++)
        P[(size_t)(b0 + bb) * O4] = acc[bb];
}

// ---------------------------------------------------------------------------
// Kernel 2: reduce NS partials + bias term.
// out[b,o] = eps_bias[b,o]*softplus(ro_bias[o]) + mu_bias[o] + sum_s P[s][b][o]
// ---------------------------------------------------------------------------
__global__ __launch_bounds__(256)
void reduce_kernel(const float* __restrict__ mu_bias,
                   const float* __restrict__ ro_bias,
                   const float* __restrict__ eps_bias,
                   float* __restrict__ out) {
    int idx = blockIdx.x * blockDim.x + threadIdx.x;   // over B*OUT/4
    int o4  = idx % O4;

    float4 eb = reinterpret_cast<const float4*>(eps_bias)[idx];
    float4 rb = reinterpret_cast<const float4*>(ro_bias)[o4];
    float4 mb = reinterpret_cast<const float4*>(mu_bias)[o4];

    float4 acc;
    acc.x = fmaf(eb.x, log1pf(__expf(rb.x)), mb.x);
    acc.y = fmaf(eb.y, log1pf(__expf(rb.y)), mb.y);
    acc.z = fmaf(eb.z, log1pf(__expf(rb.z)), mb.z);
    acc.w = fmaf(eb.w, log1pf(__expf(rb.w)), mb.w);

#pragma unroll
    for (int s = 0; s < NS; s++) {
        float4 p = reinterpret_cast<const float4*>(g_partial)[(size_t)s * BB * O4 + idx];
        acc.x += p.x; acc.y += p.y; acc.z += p.z; acc.w += p.w;
    }
    reinterpret_cast<float4*>(out)[idx] = acc;
}

// ---------------------------------------------------------------------------
// Launch. Input order (metadata): x, mu, ro, mu_bias, ro_bias, eps, eps_bias
// ---------------------------------------------------------------------------
extern "C" void kernel_launch(void* const* d_in, const int* in_sizes, int n_in,
                              void* d_out, int out_size) {
    const float* x        = (const float*)d_in[0];
    const float* mu       = (const float*)d_in[1];
    const float* ro       = (const float*)d_in[2];
    const float* mu_bias  = (const float*)d_in[3];
    const float* ro_bias  = (const float*)d_in[4];
    const float* eps      = (const float*)d_in[5];
    const float* eps_bias = (const float*)d_in[6];
    float* out = (float*)d_out;

    // K0: sigma precompute — IN*OUT/16 float4-quads per thread-block grid
    sigma_kernel<<<(IN_ * OUT_ / 16) / 256, 256>>>(ro);

    // K1: main streaming kernel, grid = NS x NBG = 128 blocks, single wave
    dim3 grid(NS, NBG);
    main_kernel<<<grid, 256>>>(x, mu, eps);

    // K2: reduce + bias (B*OUT/4 = 32768 lanes)
    reduce_kernel<<<(BB * OUT_ / 4) / 256, 256>>>(mu_bias, ro_bias, eps_bias, out);
}

// round 3
// speedup vs baseline: 2.6239x; 2.6239x over previous
#include <cuda_runtime.h>
#include <cstdint>

// Problem constants
#define BB   128      // batch
#define IN_  1024
#define OUT_ 1024
#define NS   16       // i-dimension splits
#define LI   (IN_/NS) // 64 i-values per split
#define OG   16       // o-dimension groups
#define OT   64       // o-values per block (16 float4)
#define O4   (OUT_/4) // 256 float4 lanes over OUT

// Scratch (allocation-free rule: __device__ global)
__device__ float g_partial[NS * BB * OUT_];      // per-split partial sums, 8 MB

// ---------------------------------------------------------------------------
// Main streaming kernel. Block (s, og): i in [s*LI,(s+1)*LI), o-tile of 64,
// ALL 128 batches accumulated in a 32KB smem tile. sigma/mu/ro are read by
// exactly ONE block each (no cross-block replication -> minimal L2 traffic);
// softplus(ro) fused (redundant per-warp MUFU is negligible).
// Thread (g=t>>4, l=t&15) exclusively owns acc[b = g mod 16][4 o's] -> no
// __syncthreads anywhere; ii=0 peeled as pure store (no zeroing pass).
// ---------------------------------------------------------------------------
__global__ __launch_bounds__(256, 2)
void main_kernel(const float* __restrict__ x,
                 const float* __restrict__ mu,
                 const float* __restrict__ ro,
                 const float* __restrict__ eps) {
    __shared__ float4 sacc[BB][OT / 4];   // 32 KB

    const int s  = blockIdx.x;            // 0..NS-1
    const int og = blockIdx.y;            // 0..OG-1
    const int t  = threadIdx.x;
    const int l  = t & 15;                // o-lane (float4) within tile
    const int g  = t >> 4;                // batch class: b in {g, g+16, ...}
    const int i0 = s * LI;
    const int oc = og * (OT / 4) + l;     // float4 column in [0, O4)

    const float4* mu4 = reinterpret_cast<const float4*>(mu)  + (size_t)i0 * O4 + oc;
    const float4* ro4 = reinterpret_cast<const float4*>(ro)  + (size_t)i0 * O4 + oc;
    const float4* ep4 = reinterpret_cast<const float4*>(eps) + (size_t)i0 * O4 + oc;
    const float*  xp  = x + i0;

    // ---- ii = 0 peeled: pure store (initializes sacc, no zero pass) ----
    {
        float4 ev[8];
        float  xv[8];
#pragma unroll
        for (int k = 0; k < 8; k++) {
            const int b = g + 16 * k;
            ev[k] = ep4[(size_t)b * IN_ * O4];
            xv[k] = xp[(size_t)b * IN_];
        }
        const float4 rr = ro4[0];
        const float4 mw = mu4[0];
        float4 sg;
        sg.x = log1pf(__expf(rr.x));
        sg.y = log1pf(__expf(rr.y));
        sg.z = log1pf(__expf(rr.z));
        sg.w = log1pf(__expf(rr.w));
#pragma unroll
        for (int k = 0; k < 8; k++) {
            const int b = g + 16 * k;
            float4 a;
            a.x = xv[k] * fmaf(ev[k].x, sg.x, mw.x);
            a.y = xv[k] * fmaf(ev[k].y, sg.y, mw.y);
            a.z = xv[k] * fmaf(ev[k].z, sg.z, mw.z);
            a.w = xv[k] * fmaf(ev[k].w, sg.w, mw.w);
            sacc[b][l] = a;
        }
    }

    // ---- ii = 1 .. LI-1: RMW into private smem cells ----
#pragma unroll 2
    for (int ii = 1; ii < LI; ii++) {
        float4 ev[8];
        float  xv[8];
#pragma unroll
        for (int k = 0; k < 8; k++) {
            const int b = g + 16 * k;
            ev[k] = ep4[((size_t)b * IN_ + ii) * O4];
            xv[k] = xp[(size_t)b * IN_ + ii];
        }
        const float4 rr = ro4[(size_t)ii * O4];
        const float4 mw = mu4[(size_t)ii * O4];
        float4 sg;
        sg.x = log1pf(__expf(rr.x));
        sg.y = log1pf(__expf(rr.y));
        sg.z = log1pf(__expf(rr.z));
        sg.w = log1pf(__expf(rr.w));
#pragma unroll
        for (int k = 0; k < 8; k++) {
            const int b = g + 16 * k;
            float4 a = sacc[b][l];
            a.x = fmaf(xv[k], fmaf(ev[k].x, sg.x, mw.x), a.x);
            a.y = fmaf(xv[k], fmaf(ev[k].y, sg.y, mw.y), a.y);
            a.z = fmaf(xv[k], fmaf(ev[k].z, sg.z, mw.z), a.z);
            a.w = fmaf(xv[k], fmaf(ev[k].w, sg.w, mw.w), a.w);
            sacc[b][l] = a;
        }
    }

    // ---- write partials P[s][b][o] (only own cells -> no sync needed) ----
    float4* P = reinterpret_cast<float4*>(g_partial) + (size_t)s * BB * O4 + oc;
#pragma unroll
    for (int k = 0; k < 8; k++) {
        const int b = g + 16 * k;
        P[(size_t)b * O4] = sacc[b][l];
    }
}

// ---------------------------------------------------------------------------
// Reduce NS partials + bias term.
// out[b,o] = eps_bias[b,o]*softplus(ro_bias[o]) + mu_bias[o] + sum_s P[s][b][o]
// ---------------------------------------------------------------------------
__global__ __launch_bounds__(256)
void reduce_kernel(const float* __restrict__ mu_bias,
                   const float* __restrict__ ro_bias,
                   const float* __restrict__ eps_bias,
                   float* __restrict__ out) {
    int idx = blockIdx.x * blockDim.x + threadIdx.x;   // over B*OUT/4
    int o4  = idx % O4;

    float4 eb = reinterpret_cast<const float4*>(eps_bias)[idx];
    float4 rb = reinterpret_cast<const float4*>(ro_bias)[o4];
    float4 mb = reinterpret_cast<const float4*>(mu_bias)[o4];

    float4 acc;
    acc.x = fmaf(eb.x, log1pf(__expf(rb.x)), mb.x);
    acc.y = fmaf(eb.y, log1pf(__expf(rb.y)), mb.y);
    acc.z = fmaf(eb.z, log1pf(__expf(rb.z)), mb.z);
    acc.w = fmaf(eb.w, log1pf(__expf(rb.w)), mb.w);

#pragma unroll
    for (int s = 0; s < NS; s++) {
        float4 p = reinterpret_cast<const float4*>(g_partial)[(size_t)s * BB * O4 + idx];
        acc.x += p.x; acc.y += p.y; acc.z += p.z; acc.w += p.w;
    }
    reinterpret_cast<float4*>(out)[idx] = acc;
}

// ---------------------------------------------------------------------------
// Launch. Input order (metadata): x, mu, ro, mu_bias, ro_bias, eps, eps_bias
// ---------------------------------------------------------------------------
extern "C" void kernel_launch(void* const* d_in, const int* in_sizes, int n_in,
                              void* d_out, int out_size) {
    const float* x        = (const float*)d_in[0];
    const float* mu       = (const float*)d_in[1];
    const float* ro       = (const float*)d_in[2];
    const float* mu_bias  = (const float*)d_in[3];
    const float* ro_bias  = (const float*)d_in[4];
    const float* eps      = (const float*)d_in[5];
    const float* eps_bias = (const float*)d_in[6];
    float* out = (float*)d_out;

    // Main streaming kernel: grid = NS x OG = 256 blocks, 2/SM, single wave
    dim3 grid(NS, OG);
    main_kernel<<<grid, 256>>>(x, mu, ro, eps);

    // Reduce + bias (B*OUT/4 = 32768 lanes)
    reduce_kernel<<<(BB * OUT_ / 4) / 256, 256>>>(mu_bias, ro_bias, eps_bias, out);
}

// round 4
// speedup vs baseline: 2.6615x; 1.0143x over previous
#include <cuda_runtime.h>
#include <cstdint>

// Problem constants
#define BB   128      // batch
#define IN_  1024
#define OUT_ 1024
#define NS   16       // i-dimension splits
#define LI   (IN_/NS) // 64 i-values per split
#define NB   16       // batches per block
#define NBG  (BB/NB)  // 8 batch groups
#define OT   512      // outs per block
#define OTG  (OUT_/OT)// 2 out groups
#define O4   (OUT_/4) // 256 float4 lanes over full OUT
#define OT4  (OT/4)   // 128 float4 lanes per block

// Scratch (allocation-free rule: __device__ global)
__device__ float g_partial[NS * BB * OUT_];   // per-split partials, 8 MB

// ---------------------------------------------------------------------------
// Main streaming kernel. Block (s, bg, z): i in [s*LI,(s+1)*LI),
// batches [bg*16, bg*16+16), outs [z*512, z*512+512).
// Register accumulators: thread (g=t>>7, l=t&127) owns 8 batches
// (b = g+2k) x 1 float4 of outs -> acc[8] = 32 floats (R1's proven footprint,
// no spills). x staged through 4KB smem (LDS broadcast, no scalar LDGs).
// softplus(ro) fused. mu/ro L2 replication = NBG = 8x (L2-resident).
// ---------------------------------------------------------------------------
__global__ __launch_bounds__(256, 2)
void main_kernel(const float* __restrict__ x,
                 const float* __restrict__ mu,
                 const float* __restrict__ ro,
                 const float* __restrict__ eps) {
    __shared__ float xs[NB][LI];          // 4 KB

    const int s  = blockIdx.x;            // 0..NS-1
    const int bg = blockIdx.y;            // 0..NBG-1
    const int z  = blockIdx.z;            // 0..OTG-1
    const int t  = threadIdx.x;
    const int l  = t & (OT4 - 1);         // o float4 lane within block
    const int g  = t >> 7;                // 0..1 batch class
    const int i0 = s * LI;
    const int b0 = bg * NB;
    const int oc = z * OT4 + l;           // float4 column in [0, O4)

    // Cooperative float4 load of x tile [16 b][64 i]
    {
        const int row = t >> 4;           // 0..15
        const int col = (t & 15) * 4;     // 0..60
        float4 v = *reinterpret_cast<const float4*>(
            x + (size_t)(b0 + row) * IN_ + i0 + col);
        *reinterpret_cast<float4*>(&xs[row][col]) = v;
    }
    __syncthreads();

    const float4* mu4 = reinterpret_cast<const float4*>(mu)  + (size_t)i0 * O4 + oc;
    const float4* ro4 = reinterpret_cast<const float4*>(ro)  + (size_t)i0 * O4 + oc;
    const float4* ep4 = reinterpret_cast<const float4*>(eps)
                        + ((size_t)b0 * IN_ + i0) * O4 + oc;

    float4 acc[8];

    // ---- ii = 0 peeled: pure multiply (initializes acc) ----
    {
        float4 ev[8];
#pragma unroll
        for (int k = 0; k < 8; k++) {
            const int lb = g + 2 * k;
            ev[k] = ep4[(size_t)lb * IN_ * O4];
        }
        const float4 rr = ro4[0];
        const float4 mw = mu4[0];
        float4 sg;
        sg.x = log1pf(__expf(rr.x));
        sg.y = log1pf(__expf(rr.y));
        sg.z = log1pf(__expf(rr.z));
        sg.w = log1pf(__expf(rr.w));
#pragma unroll
        for (int k = 0; k < 8; k++) {
            const int lb = g + 2 * k;
            const float xr = xs[lb][0];
            acc[k].x = xr * fmaf(ev[k].x, sg.x, mw.x);
            acc[k].y = xr * fmaf(ev[k].y, sg.y, mw.y);
            acc[k].z = xr * fmaf(ev[k].z, sg.z, mw.z);
            acc[k].w = xr * fmaf(ev[k].w, sg.w, mw.w);
        }
    }

    // ---- ii = 1 .. LI-1 ----
#pragma unroll 1
    for (int ii = 1; ii < LI; ii++) {
        float4 ev[8];
#pragma unroll
        for (int k = 0; k < 8; k++) {
            const int lb = g + 2 * k;
            ev[k] = ep4[((size_t)lb * IN_ + ii) * O4];
        }
        const float4 rr = ro4[(size_t)ii * O4];
        const float4 mw = mu4[(size_t)ii * O4];
        float4 sg;
        sg.x = log1pf(__expf(rr.x));
        sg.y = log1pf(__expf(rr.y));
        sg.z = log1pf(__expf(rr.z));
        sg.w = log1pf(__expf(rr.w));
#pragma unroll
        for (int k = 0; k < 8; k++) {
            const int lb = g + 2 * k;
            const float xr = xs[lb][ii];
            acc[k].x = fmaf(xr, fmaf(ev[k].x, sg.x, mw.x), acc[k].x);
            acc[k].y = fmaf(xr, fmaf(ev[k].y, sg.y, mw.y), acc[k].y);
            acc[k].z = fmaf(xr, fmaf(ev[k].z, sg.z, mw.z), acc[k].z);
            acc[k].w = fmaf(xr, fmaf(ev[k].w, sg.w, mw.w), acc[k].w);
        }
    }

    // ---- write partials P[s][b][o] ----
    float4* P = reinterpret_cast<float4*>(g_partial)
                + ((size_t)s * BB + b0) * O4 + oc;
#pragma unroll
    for (int k = 0; k < 8; k++) {
        const int lb = g + 2 * k;
        P[(size_t)lb * O4] = acc[k];
    }
}

// ---------------------------------------------------------------------------
// Reduce NS partials + bias term (scalar; 512 blocks for latency hiding).
// out[b,o] = eps_bias[b,o]*softplus(ro_bias[o]) + mu_bias[o] + sum_s P[s][b][o]
// ---------------------------------------------------------------------------
__global__ __launch_bounds__(256)
void reduce_kernel(const float* __restrict__ mu_bias,
                   const float* __restrict__ ro_bias,
                   const float* __restrict__ eps_bias,
                   float* __restrict__ out) {
    const int idx = blockIdx.x * blockDim.x + threadIdx.x;   // over B*OUT
    const int o   = idx & (OUT_ - 1);

    const float eb = eps_bias[idx];
    const float rb = ro_bias[o];
    const float mb = mu_bias[o];

    float acc = fmaf(eb, log1pf(__expf(rb)), mb);
#pragma unroll
    for (int s = 0; s < NS; s++)
        acc += g_partial[(size_t)s * BB * OUT_ + idx];
    out[idx] = acc;
}

// ---------------------------------------------------------------------------
// Launch. Input order (metadata): x, mu, ro, mu_bias, ro_bias, eps, eps_bias
// ---------------------------------------------------------------------------
extern "C" void kernel_launch(void* const* d_in, const int* in_sizes, int n_in,
                              void* d_out, int out_size) {
    const float* x        = (const float*)d_in[0];
    const float* mu       = (const float*)d_in[1];
    const float* ro       = (const float*)d_in[2];
    const float* mu_bias  = (const float*)d_in[3];
    const float* ro_bias  = (const float*)d_in[4];
    const float* eps      = (const float*)d_in[5];
    const float* eps_bias = (const float*)d_in[6];
    float* out = (float*)d_out;

    // Main: grid = NS x NBG x OTG = 16 x 8 x 2 = 256 blocks, 2/SM, one wave
    dim3 grid(NS, NBG, OTG);
    main_kernel<<<grid, 256>>>(x, mu, ro, eps);

    // Reduce + bias: B*OUT = 131072 threads
    reduce_kernel<<<(BB * OUT_) / 256, 256>>>(mu_bias, ro_bias, eps_bias, out);
}

// round 5
// speedup vs baseline: 2.6846x; 1.0087x over previous
#include <cuda_runtime.h>
#include <cstdint>

// Problem constants
#define BB   128        // batch
#define IN_  1024
#define OUT_ 1024
#define NS   16         // i-dimension splits
#define LI   (IN_/NS)   // 64 i-values per split
#define NB   8          // batches per block
#define NBG  (BB/NB)    // 16 batch groups
#define OT   256        // outs per block
#define OTG  (OUT_/OT)  // 4 out groups
#define O4   (OUT_/4)   // 256 float4 lanes over full OUT
#define OT4  (OT/4)     // 64 float4 lanes per block

// Scratch (allocation-free rule: __device__ global)
__device__ float g_partial[NS * BB * OUT_];   // per-split partials, 8 MB

// ---------------------------------------------------------------------------
// Main streaming kernel. Grid = NS*NBG*OTG = 1024 blocks of 128 threads at
// occupancy 7 -> ~6.9 blocks/SM, ~1% wave imbalance (vs 15.6% at 256 blocks
// occ 2, which left 20 SMs underused). Thread (g=t>>6, l=t&63) owns 4 batches
// (lb = g+2k) x 1 float4 of outs -> acc[4] = 16 regs. x staged via 2KB smem.
// softplus(ro) fused. s==0 blocks fold the bias term into their partial so
// the reduce kernel is a pure 16-way sum.
// ---------------------------------------------------------------------------
__global__ __launch_bounds__(128, 7)
void main_kernel(const float* __restrict__ x,
                 const float* __restrict__ mu,
                 const float* __restrict__ ro,
                 const float* __restrict__ eps,
                 const float* __restrict__ mu_bias,
                 const float* __restrict__ ro_bias,
                 const float* __restrict__ eps_bias) {
    __shared__ float xs[NB][LI];          // 2 KB

    const int bx = blockIdx.x;            // 0..1023
    const int s  = bx & (NS - 1);         // 0..15
    const int bg = (bx >> 4) & (NBG - 1); // 0..15
    const int z  = bx >> 8;               // 0..3
    const int t  = threadIdx.x;
    const int l  = t & (OT4 - 1);         // o float4 lane within block (0..63)
    const int g  = t >> 6;                // 0..1 batch class
    const int i0 = s * LI;
    const int b0 = bg * NB;
    const int oc = z * OT4 + l;           // float4 column in [0, O4)

    // Cooperative float4 load of x tile [8 b][64 i]: 128 float4s, one each
    {
        const int row = t >> 4;           // 0..7
        const int col = (t & 15) * 4;     // 0..60
        float4 v = *reinterpret_cast<const float4*>(
            x + (size_t)(b0 + row) * IN_ + i0 + col);
        *reinterpret_cast<float4*>(&xs[row][col]) = v;
    }
    __syncthreads();

    const float4* mu4 = reinterpret_cast<const float4*>(mu)  + (size_t)i0 * O4 + oc;
    const float4* ro4 = reinterpret_cast<const float4*>(ro)  + (size_t)i0 * O4 + oc;
    const float4* ep4 = reinterpret_cast<const float4*>(eps)
                        + ((size_t)b0 * IN_ + i0) * O4 + oc;

    float4 acc[4];

    // ---- ii = 0 peeled: pure multiply (initializes acc) ----
    {
        float4 ev[4];
#pragma unroll
        for (int k = 0; k < 4; k++) {
            const int lb = g + 2 * k;
            ev[k] = ep4[(size_t)lb * IN_ * O4];
        }
        const float4 rr = ro4[0];
        const float4 mw = mu4[0];
        float4 sg;
        sg.x = log1pf(__expf(rr.x));
        sg.y = log1pf(__expf(rr.y));
        sg.z = log1pf(__expf(rr.z));
        sg.w = log1pf(__expf(rr.w));
#pragma unroll
        for (int k = 0; k < 4; k++) {
            const int lb = g + 2 * k;
            const float xr = xs[lb][0];
            acc[k].x = xr * fmaf(ev[k].x, sg.x, mw.x);
            acc[k].y = xr * fmaf(ev[k].y, sg.y, mw.y);
            acc[k].z = xr * fmaf(ev[k].z, sg.z, mw.z);
            acc[k].w = xr * fmaf(ev[k].w, sg.w, mw.w);
        }
    }

    // ---- ii = 1 .. LI-1 ----
#pragma unroll 1
    for (int ii = 1; ii < LI; ii++) {
        float4 ev[4];
#pragma unroll
        for (int k = 0; k < 4; k++) {
            const int lb = g + 2 * k;
            ev[k] = ep4[((size_t)lb * IN_ + ii) * O4];
        }
        const float4 rr = ro4[(size_t)ii * O4];
        const float4 mw = mu4[(size_t)ii * O4];
        float4 sg;
        sg.x = log1pf(__expf(rr.x));
        sg.y = log1pf(__expf(rr.y));
        sg.z = log1pf(__expf(rr.z));
        sg.w = log1pf(__expf(rr.w));
#pragma unroll
        for (int k = 0; k < 4; k++) {
            const int lb = g + 2 * k;
            const float xr = xs[lb][ii];
            acc[k].x = fmaf(xr, fmaf(ev[k].x, sg.x, mw.x), acc[k].x);
            acc[k].y = fmaf(xr, fmaf(ev[k].y, sg.y, mw.y), acc[k].y);
            acc[k].z = fmaf(xr, fmaf(ev[k].z, sg.z, mw.z), acc[k].z);
            acc[k].w = fmaf(xr, fmaf(ev[k].w, sg.w, mw.w), acc[k].w);
        }
    }

    // ---- s==0 blocks fold in the bias term:
    //      bias[b,o] = eps_bias[b,o]*softplus(ro_bias[o]) + mu_bias[o] ----
    if (s == 0) {
        const float4 rb = reinterpret_cast<const float4*>(ro_bias)[oc];
        const float4 mb = reinterpret_cast<const float4*>(mu_bias)[oc];
        float4 sb;
        sb.x = log1pf(__expf(rb.x));
        sb.y = log1pf(__expf(rb.y));
        sb.z = log1pf(__expf(rb.z));
        sb.w = log1pf(__expf(rb.w));
#pragma unroll
        for (int k = 0; k < 4; k++) {
            const int lb = g + 2 * k;
            const float4 eb = reinterpret_cast<const float4*>(eps_bias)
                                  [(size_t)(b0 + lb) * O4 + oc];
            acc[k].x = fmaf(eb.x, sb.x, acc[k].x + mb.x);
            acc[k].y = fmaf(eb.y, sb.y, acc[k].y + mb.y);
            acc[k].z = fmaf(eb.z, sb.z, acc[k].z + mb.z);
            acc[k].w = fmaf(eb.w, sb.w, acc[k].w + mb.w);
        }
    }

    // ---- write partials P[s][b][o] ----
    float4* P = reinterpret_cast<float4*>(g_partial)
                + ((size_t)s * BB + b0) * O4 + oc;
#pragma unroll
    for (int k = 0; k < 4; k++) {
        const int lb = g + 2 * k;
        P[(size_t)lb * O4] = acc[k];
    }
}

// ---------------------------------------------------------------------------
// Reduce: pure 16-way partial sum (bias already folded into s==0 partials).
// float4 per thread, 16 independent loads in flight; partials are L2-hot.
// ---------------------------------------------------------------------------
__global__ __launch_bounds__(128)
void reduce_kernel(float* __restrict__ out) {
    const int idx = blockIdx.x * blockDim.x + threadIdx.x;   // over BB*O4
    const float4* P = reinterpret_cast<const float4*>(g_partial) + idx;

    float4 acc = P[0];
#pragma unroll
    for (int s = 1; s < NS; s++) {
        float4 p = P[(size_t)s * BB * O4];
        acc.x += p.x; acc.y += p.y; acc.z += p.z; acc.w += p.w;
    }
    reinterpret_cast<float4*>(out)[idx] = acc;
}

// ---------------------------------------------------------------------------
// Launch. Input order (metadata): x, mu, ro, mu_bias, ro_bias, eps, eps_bias
// ---------------------------------------------------------------------------
extern "C" void kernel_launch(void* const* d_in, const int* in_sizes, int n_in,
                              void* d_out, int out_size) {
    const float* x        = (const float*)d_in[0];
    const float* mu       = (const float*)d_in[1];
    const float* ro       = (const float*)d_in[2];
    const float* mu_bias  = (const float*)d_in[3];
    const float* ro_bias  = (const float*)d_in[4];
    const float* eps      = (const float*)d_in[5];
    const float* eps_bias = (const float*)d_in[6];
    float* out = (float*)d_out;

    // Main: 1024 blocks x 128 threads, occ 7 -> ~1% wave imbalance
    main_kernel<<<NS * NBG * OTG, 128>>>(x, mu, ro, eps,
                                         mu_bias, ro_bias, eps_bias);

    // Reduce: BB*O4 = 32768 float4 lanes
    reduce_kernel<<<(BB * O4) / 128, 128>>>(out);
}

// round 6
// speedup vs baseline: 2.6866x; 1.0007x over previous
#include <cuda_runtime.h>
#include <cstdint>

// Problem constants
#define BB   128        // batch
#define IN_  1024
#define OUT_ 1024
#define NS   16         // i-dimension splits
#define LI   (IN_/NS)   // 64 i-values per split
#define NB   8          // batches per block
#define NBG  (BB/NB)    // 16 batch groups
#define OT   256        // outs per block
#define OTG  (OUT_/OT)  // 4 out groups
#define O4   (OUT_/4)   // 256 float4 lanes over full OUT
#define OT4  (OT/4)     // 64 float4 lanes per block

// Scratch (allocation-free rule: __device__ globals)
__device__ float g_partial[NS * BB * OUT_];   // per-split partials, 8 MB
__device__ int   g_count[NBG * OTG];          // tile completion counters
                                              // (zero-init; finisher resets)

// ---------------------------------------------------------------------------
// Fused streaming + reduction kernel. Grid = NS*NBG*OTG = 1024 blocks of 128
// threads at occ 7. Block (s,bg,z): i in [s*LI,(s+1)*LI), batches
// [bg*8,bg*8+8), outs [z*256,z*256+256). Thread (g=t>>6,l=t&63) owns 4
// batches (lb=g+2k) x 1 float4 of outs -> acc[4]=16 regs. x staged via 2KB
// smem. softplus(ro) fused; bias folded into s==0 partials. eps loads use
// __ldcs (evict-first) so the 512MB stream doesn't evict partials from L2.
// The LAST s-block per (bg,z) tile re-reads all 16 partials in fixed s-order
// (deterministic FP sum) and writes out — no separate reduce kernel.
// ---------------------------------------------------------------------------
__global__ __launch_bounds__(128, 7)
void main_kernel(const float* __restrict__ x,
                 const float* __restrict__ mu,
                 const float* __restrict__ ro,
                 const float* __restrict__ eps,
                 const float* __restrict__ mu_bias,
                 const float* __restrict__ ro_bias,
                 const float* __restrict__ eps_bias,
                 float* __restrict__ out) {
    __shared__ float xs[NB][LI];          // 2 KB
    __shared__ int   s_last;

    const int bx = blockIdx.x;            // 0..1023
    const int s  = bx & (NS - 1);         // 0..15
    const int bg = (bx >> 4) & (NBG - 1); // 0..15
    const int z  = bx >> 8;               // 0..3
    const int t  = threadIdx.x;
    const int l  = t & (OT4 - 1);         // o float4 lane (0..63)
    const int g  = t >> 6;                // 0..1 batch class
    const int i0 = s * LI;
    const int b0 = bg * NB;
    const int oc = z * OT4 + l;           // float4 column in [0, O4)

    // Cooperative float4 load of x tile [8 b][64 i]: 128 float4s, one each
    {
        const int row = t >> 4;           // 0..7
        const int col = (t & 15) * 4;     // 0..60
        float4 v = *reinterpret_cast<const float4*>(
            x + (size_t)(b0 + row) * IN_ + i0 + col);
        *reinterpret_cast<float4*>(&xs[row][col]) = v;
    }
    __syncthreads();

    const float4* mu4 = reinterpret_cast<const float4*>(mu)  + (size_t)i0 * O4 + oc;
    const float4* ro4 = reinterpret_cast<const float4*>(ro)  + (size_t)i0 * O4 + oc;
    const float4* ep4 = reinterpret_cast<const float4*>(eps)
                        + ((size_t)b0 * IN_ + i0) * O4 + oc;

    float4 acc[4];

    // ---- ii = 0 peeled: pure multiply (initializes acc) ----
    {
        float4 ev[4];
#pragma unroll
        for (int k = 0; k < 4; k++) {
            const int lb = g + 2 * k;
            ev[k] = __ldcs(&ep4[(size_t)lb * IN_ * O4]);
        }
        const float4 rr = ro4[0];
        const float4 mw = mu4[0];
        float4 sg;
        sg.x = log1pf(__expf(rr.x));
        sg.y = log1pf(__expf(rr.y));
        sg.z = log1pf(__expf(rr.z));
        sg.w = log1pf(__expf(rr.w));
#pragma unroll
        for (int k = 0; k < 4; k++) {
            const int lb = g + 2 * k;
            const float xr = xs[lb][0];
            acc[k].x = xr * fmaf(ev[k].x, sg.x, mw.x);
            acc[k].y = xr * fmaf(ev[k].y, sg.y, mw.y);
            acc[k].z = xr * fmaf(ev[k].z, sg.z, mw.z);
            acc[k].w = xr * fmaf(ev[k].w, sg.w, mw.w);
        }
    }

    // ---- ii = 1 .. LI-1 ----
#pragma unroll 1
    for (int ii = 1; ii < LI; ii++) {
        float4 ev[4];
#pragma unroll
        for (int k = 0; k < 4; k++) {
            const int lb = g + 2 * k;
            ev[k] = __ldcs(&ep4[((size_t)lb * IN_ + ii) * O4]);
        }
        const float4 rr = ro4[(size_t)ii * O4];
        const float4 mw = mu4[(size_t)ii * O4];
        float4 sg;
        sg.x = log1pf(__expf(rr.x));
        sg.y = log1pf(__expf(rr.y));
        sg.z = log1pf(__expf(rr.z));
        sg.w = log1pf(__expf(rr.w));
#pragma unroll
        for (int k = 0; k < 4; k++) {
            const int lb = g + 2 * k;
            const float xr = xs[lb][ii];
            acc[k].x = fmaf(xr, fmaf(ev[k].x, sg.x, mw.x), acc[k].x);
            acc[k].y = fmaf(xr, fmaf(ev[k].y, sg.y, mw.y), acc[k].y);
            acc[k].z = fmaf(xr, fmaf(ev[k].z, sg.z, mw.z), acc[k].z);
            acc[k].w = fmaf(xr, fmaf(ev[k].w, sg.w, mw.w), acc[k].w);
        }
    }

    // ---- s==0 blocks fold in the bias term ----
    if (s == 0) {
        const float4 rb = reinterpret_cast<const float4*>(ro_bias)[oc];
        const float4 mb = reinterpret_cast<const float4*>(mu_bias)[oc];
        float4 sb;
        sb.x = log1pf(__expf(rb.x));
        sb.y = log1pf(__expf(rb.y));
        sb.z = log1pf(__expf(rb.z));
        sb.w = log1pf(__expf(rb.w));
#pragma unroll
        for (int k = 0; k < 4; k++) {
            const int lb = g + 2 * k;
            const float4 eb = reinterpret_cast<const float4*>(eps_bias)
                                  [(size_t)(b0 + lb) * O4 + oc];
            acc[k].x = fmaf(eb.x, sb.x, acc[k].x + mb.x);
            acc[k].y = fmaf(eb.y, sb.y, acc[k].y + mb.y);
            acc[k].z = fmaf(eb.z, sb.z, acc[k].z + mb.z);
            acc[k].w = fmaf(eb.w, sb.w, acc[k].w + mb.w);
        }
    }

    // ---- write partials P[s][b][o] ----
    float4* Pbase = reinterpret_cast<float4*>(g_partial);
#pragma unroll
    for (int k = 0; k < 4; k++) {
        const int lb = g + 2 * k;
        Pbase[((size_t)s * BB + b0 + lb) * O4 + oc] = acc[k];
    }

    // ---- last-block-done: 16th arriver for this (bg,z) tile reduces ----
    __threadfence();                       // release: partials visible
    __syncthreads();
    if (t == 0) {
        int prev = atomicAdd(&g_count[bg * OTG + z], 1);
        s_last = (prev == NS - 1);
    }
    __syncthreads();
    if (s_last) {
        __threadfence();                   // acquire: see all 16 partials
        if (t == 0) g_count[bg * OTG + z] = 0;   // reset for next replay
#pragma unroll
        for (int k = 0; k < 4; k++) {
            const int lb = g + 2 * k;
            const float4* Pc = Pbase + ((size_t)b0 + lb) * O4 + oc;
            // Fixed s-ascending order -> deterministic FP sum
            float4 r = Pc[0];
#pragma unroll
            for (int ss = 1; ss < NS; ss++) {
                float4 p = Pc[(size_t)ss * BB * O4];
                r.x += p.x; r.y += p.y; r.z += p.z; r.w += p.w;
            }
            reinterpret_cast<float4*>(out)[(size_t)(b0 + lb) * O4 + oc] = r;
        }
    }
}

// ---------------------------------------------------------------------------
// Launch. Input order (metadata): x, mu, ro, mu_bias, ro_bias, eps, eps_bias
// ---------------------------------------------------------------------------
extern "C" void kernel_launch(void* const* d_in, const int* in_sizes, int n_in,
                              void* d_out, int out_size) {
    const float* x        = (const float*)d_in[0];
    const float* mu       = (const float*)d_in[1];
    const float* ro       = (const float*)d_in[2];
    const float* mu_bias  = (const float*)d_in[3];
    const float* ro_bias  = (const float*)d_in[4];
    const float* eps      = (const float*)d_in[5];
    const float* eps_bias = (const float*)d_in[6];
    float* out = (float*)d_out;

    // Single fused kernel: 1024 blocks x 128 threads, occ 7
    main_kernel<<<NS * NBG * OTG, 128>>>(x, mu, ro, eps,
                                         mu_bias, ro_bias, eps_bias, out);
}